// round 17
// baseline (speedup 1.0000x reference)
#include <cuda_runtime.h>
#include <cstdint>

#define T_SEQ 1024
#define BATCH 256
#define ISZ   128
#define HSZ   64
#define GSZ   256   // 4*H
#define NBP   128   // BATCH/2 (batch pairs)
#define NCLS  10
#define NGRP  128   // T_SEQ/8 groups
#define WPITCH 132  // padded k-pitch (words) for conflict-free frag LDS
#define RPITCH 260  // ring row pitch in float2 units
#define NTHR  384   // 256 consumer + 128 producer threads

typedef unsigned long long ull;

// final hidden, packed pairs (cls kernel input)
__device__ ull g_hT[NBP * HSZ];

// ---------- helpers ----------
union F2U { float2 f2; ull u; };

__device__ __forceinline__ ull pack2(float lo, float hi) {
    F2U t; t.f2 = make_float2(lo, hi); return t.u;
}
__device__ __forceinline__ float2 unpack2(ull v) {
    F2U t; t.u = v; return t.f2;
}
__device__ __forceinline__ ull ffma2(ull a, ull b, ull c) {
    ull d;
    asm("fma.rn.f32x2 %0, %1, %2, %3;" : "=l"(d) : "l"(a), "l"(b), "l"(c));
    return d;
}
__device__ __forceinline__ ull fadd2(ull a, ull b) {
    ull d;
    asm("add.rn.f32x2 %0, %1, %2;" : "=l"(d) : "l"(a), "l"(b));
    return d;
}
__device__ __forceinline__ unsigned f2tf32(float f) {
    unsigned r;
    asm("cvt.rna.tf32.f32 %0, %1;" : "=r"(r) : "f"(f));
    return r;
}
__device__ __forceinline__ float ex2_ap(float x) {
    float y; asm("ex2.approx.f32 %0, %1;" : "=f"(y) : "f"(x)); return y;
}
__device__ __forceinline__ float rcp_ap(float x) {
    float y; asm("rcp.approx.f32 %0, %1;" : "=f"(y) : "f"(x)); return y;
}
// tanh(x) = 1 - 2/(1+2^(2x*log2e)) : branch-free
__device__ __forceinline__ float tanh_f(float x) {
    return fmaf(-2.0f, rcp_ap(1.0f + ex2_ap(2.8853900817779268f * x)), 1.0f);
}

#define BAR_CONS() asm volatile("bar.sync 1, 256;" ::: "memory")
#define BAR_PROD() asm volatile("bar.sync 3, 128;" ::: "memory")

#define MMA_TF32(D, A0, A1, A2, A3, B0, B1)                            \
    asm volatile(                                                      \
        "mma.sync.aligned.m16n8k8.row.col.f32.tf32.tf32.f32 "          \
        "{%0,%1,%2,%3}, {%4,%5,%6,%7}, {%8,%9}, {%0,%1,%2,%3};"        \
        : "+f"((D)[0]), "+f"((D)[1]), "+f"((D)[2]), "+f"((D)[3])       \
        : "r"(A0), "r"(A1), "r"(A2), "r"(A3), "r"(B0), "r"(B1))

// =====================================================================
// Producer routine: 128 threads (warps 8-11) build x_proj for group P
// into ring buffer `rbuf`. Stage x (LDG->tf32->Ast), bar, W_ih GEMM on
// tensor pipe, epilogue adds bias and stores [tl][gate] float2 pairs.
// =====================================================================
__device__ __forceinline__ void produce_group(
    const float* __restrict__ x, const unsigned* __restrict__ Wst,
    unsigned* __restrict__ Ast, float* __restrict__ rbuf,
    const float* __restrict__ bias_s, int P, int tid2, int b0g)
{
    // ---- stage x: 16 rows x 128 k; thread = (row, 16-float seg) ----
    {
        const int row = tid2 >> 3;          // 0..15  (b*8 + tl)
        const int seg = tid2 & 7;           // k = seg*16
        const int b   = row >> 3, tl = row & 7;
        const float* src = &x[(((size_t)(b0g + b)) * T_SEQ + (size_t)P * 8 + tl) * ISZ + seg * 16];
        float4 v0 = *(const float4*)&src[0];
        float4 v1 = *(const float4*)&src[4];
        float4 v2 = *(const float4*)&src[8];
        float4 v3 = *(const float4*)&src[12];
        unsigned* dst = &Ast[row * WPITCH + seg * 16];
        dst[0]  = f2tf32(v0.x); dst[1]  = f2tf32(v0.y); dst[2]  = f2tf32(v0.z); dst[3]  = f2tf32(v0.w);
        dst[4]  = f2tf32(v1.x); dst[5]  = f2tf32(v1.y); dst[6]  = f2tf32(v1.z); dst[7]  = f2tf32(v1.w);
        dst[8]  = f2tf32(v2.x); dst[9]  = f2tf32(v2.y); dst[10] = f2tf32(v2.z); dst[11] = f2tf32(v2.w);
        dst[12] = f2tf32(v3.x); dst[13] = f2tf32(v3.y); dst[14] = f2tf32(v3.z); dst[15] = f2tf32(v3.w);
    }
    BAR_PROD();

    // ---- W_ih GEMM: 4 warps x 64 gate-cols each, 8 n-tiles ----
    const int pw   = tid2 >> 5;             // producer warp 0..3
    const int lane = tid2 & 31;
    const int gid  = lane >> 2, tig = lane & 3;

    float acc[8][4];
    #pragma unroll
    for (int n = 0; n < 8; n++)
        #pragma unroll
        for (int i = 0; i < 4; i++) acc[n][i] = 0.f;

    #pragma unroll
    for (int ks = 0; ks < 16; ++ks) {
        const int k0 = ks * 8;
        unsigned a0 = Ast[ gid      * WPITCH + k0 + tig];
        unsigned a1 = Ast[(gid + 8) * WPITCH + k0 + tig];
        unsigned a2 = Ast[ gid      * WPITCH + k0 + tig + 4];
        unsigned a3 = Ast[(gid + 8) * WPITCH + k0 + tig + 4];
        #pragma unroll
        for (int nt = 0; nt < 8; nt++) {
            const int nl = pw * 64 + nt * 8 + gid;
            unsigned bb0 = Wst[nl * WPITCH + k0 + tig];
            unsigned bb1 = Wst[nl * WPITCH + k0 + tig + 4];
            MMA_TF32(acc[nt], a0, a1, a2, a3, bb0, bb1);
        }
    }
    // epilogue: rows gid->(b0,tl=gid), gid+8->(b1,tl=gid); cols 2tig,2tig+1
    #pragma unroll
    for (int nt = 0; nt < 8; nt++) {
        const int nl2 = pw * 64 + nt * 8 + 2 * tig;
        const float bs0 = bias_s[nl2], bs1 = bias_s[nl2 + 1];
        float* r0 = &rbuf[(gid * RPITCH + nl2) * 2];
        r0[0] = acc[nt][0] + bs0;     // (b0, col nl2)
        r0[2] = acc[nt][1] + bs1;     // (b0, col nl2+1)
        r0[1] = acc[nt][2] + bs0;     // (b1, col nl2)
        r0[3] = acc[nt][3] + bs1;     // (b1, col nl2+1)
    }
}

// =====================================================================
// FUSED warp-specialized kernel: 128 CTAs (one batch pair), 384 threads.
// Warps 0-7: FFMA2 recurrence consuming the SMEM ring; tail (c/h update)
// spread over threads 0-127 (all 4 SMSPs, one tanh chain each).
// Warps 8-11: produce group P+1's x_proj on the tensor pipe, overlapped
// with the 8 steps of group P (double-buffered ring).
// =====================================================================
__global__ __launch_bounds__(NTHR, 1) void lstm_fused_kernel(
    const float* __restrict__ x, const float* __restrict__ W_ih,
    const float* __restrict__ W_hh,
    const float* __restrict__ b_ih, const float* __restrict__ b_hh)
{
    extern __shared__ __align__(16) unsigned smem_raw[];
    unsigned* Wst  = smem_raw;                        // 256*132 tf32 words
    unsigned* Ast  = Wst + GSZ * WPITCH;              // 16*132 tf32 words
    float*    ring = (float*)(Ast + 16 * WPITCH);     // 2 bufs * 8 * RPITCH * 2
    float*    bias_s = ring + 2 * 8 * RPITCH * 2;     // 256
    ull*      h_s  = (ull*)(bias_s + GSZ);            // 64
    ull*      gate_s = h_s + HSZ;                     // 256

    const int tid = threadIdx.x;
    const int bp  = blockIdx.x;
    const int b0g = bp * 2;

    // ---- stage W_ih -> SMEM tf32 (all 384 threads) ----
    for (int i = tid; i < GSZ * (ISZ / 4); i += NTHR) {
        int gg = i >> 5, s = i & 31;
        float4 v = ((const float4*)W_ih)[(size_t)gg * 32 + s];
        unsigned* dst = &Wst[gg * WPITCH + s * 4];
        dst[0] = f2tf32(v.x); dst[1] = f2tf32(v.y);
        dst[2] = f2tf32(v.z); dst[3] = f2tf32(v.w);
    }
    if (tid < GSZ) bias_s[tid] = b_ih[tid] + b_hh[tid];
    if (tid < HSZ) h_s[tid] = 0ull;
    __syncthreads();

    if (tid >= 256) {
        // ================= PRODUCER WARPS =================
        const int tid2 = tid - 256;
        produce_group(x, Wst, Ast, ring, bias_s, 0, tid2, b0g);   // group 0 -> buf 0
        __syncthreads();
        for (int P = 0; P < NGRP; ++P) {
            if (P + 1 < NGRP)
                produce_group(x, Wst, Ast, ring + ((P + 1) & 1) * (8 * RPITCH * 2),
                              bias_s, P + 1, tid2, b0g);
            __syncthreads();
        }
    } else {
        // ================= CONSUMER WARPS =================
        const int g   = tid;
        const int sec = g >> 6;       // 0:i 1:f 2:g 3:o (warp-uniform)
        const float kmul = (sec == 2) ? 2.8853900817779268f : 1.4426950408889634f;
        const float aco  = (sec == 2) ?  2.0f : 1.0f;
        const float bco  = (sec == 2) ? -1.0f : 0.0f;

        // W_hh row g duplicated into f32x2 pairs (128 regs)
        ull w2[HSZ];
        {
            const float4* wrow = (const float4*)&W_hh[g * HSZ];
            #pragma unroll
            for (int q = 0; q < 16; ++q) {
                float4 w = wrow[q];
                w2[q * 4 + 0] = pack2(w.x, w.x);
                w2[q * 4 + 1] = pack2(w.y, w.y);
                w2[q * 4 + 2] = pack2(w.z, w.z);
                w2[q * 4 + 3] = pack2(w.w, w.w);
            }
        }
        // tail ownership: threads 0..127 -> (j = tid>>1, cm = tid&1)
        const int tj = tid >> 1;
        const int cm = tid & 1;
        float c_st = 0.f;
        __syncthreads();              // matches producer's post-group0 barrier

        for (int P = 0; P < NGRP; ++P) {
            const float* rbuf = ring + (P & 1) * (8 * RPITCH * 2);
            for (int tl = 0; tl < 8; ++tl) {
                // acc0 initialized from xp (bias folded in by producer)
                ull acc0 = *(const ull*)&rbuf[(tl * RPITCH + g) * 2];
                ull acc1 = 0ull, acc2 = 0ull, acc3 = 0ull;
                const ulonglong2* h2 = (const ulonglong2*)h_s;
                #pragma unroll
                for (int kk = 0; kk < 16; ++kk) {
                    ulonglong2 ha = h2[2 * kk];
                    ulonglong2 hb = h2[2 * kk + 1];
                    acc0 = ffma2(w2[4 * kk + 0], ha.x, acc0);
                    acc1 = ffma2(w2[4 * kk + 1], ha.y, acc1);
                    acc2 = ffma2(w2[4 * kk + 2], hb.x, acc2);
                    acc3 = ffma2(w2[4 * kk + 3], hb.y, acc3);
                }
                ull gsum = fadd2(fadd2(acc0, acc1), fadd2(acc2, acc3));

                float2 gv = unpack2(gsum);
                float r0 = fmaf(aco, rcp_ap(1.0f + ex2_ap(-kmul * gv.x)), bco);
                float r1 = fmaf(aco, rcp_ap(1.0f + ex2_ap(-kmul * gv.y)), bco);
                gate_s[g] = pack2(r0, r1);
                BAR_CONS();

                // tail: threads 0..127 (warps 0-3), one (j, comp) each
                if (tid < 128) {
                    const float* gsf = (const float*)gate_s;
                    float iv = gsf[(      tj) * 2 + cm];
                    float fv = gsf[( 64 + tj) * 2 + cm];
                    float gg = gsf[(128 + tj) * 2 + cm];
                    float ov = gsf[(192 + tj) * 2 + cm];
                    c_st = fmaf(fv, c_st, iv * gg);
                    float h = ov * tanh_f(c_st);
                    ((float*)h_s)[tj * 2 + cm] = h;
                    if (P == NGRP - 1 && tl == 7)
                        ((float*)g_hT)[(bp * HSZ + tj) * 2 + cm] = h;
                }
                BAR_CONS();
            }
            __syncthreads();          // group boundary: swap ring buffers
        }
    }
}

// =====================================================================
// Kernel C: logits = h_T @ W_cls^T + b_cls   (256 x 10)
// =====================================================================
__global__ void cls_kernel(const float* __restrict__ W_cls,
                           const float* __restrict__ b_cls,
                           float* __restrict__ out)
{
    const int b = blockIdx.x, lane = threadIdx.x;
    const int bp = b >> 1, par = b & 1;
    float2 p0 = unpack2(g_hT[bp * HSZ + lane]);
    float2 p1 = unpack2(g_hT[bp * HSZ + lane + 32]);
    float h0 = par ? p0.y : p0.x;
    float h1 = par ? p1.y : p1.x;
    #pragma unroll
    for (int c = 0; c < NCLS; ++c) {
        float p = h0 * W_cls[c * HSZ + lane] + h1 * W_cls[c * HSZ + lane + 32];
        #pragma unroll
        for (int off = 16; off; off >>= 1)
            p += __shfl_xor_sync(0xffffffffu, p, off);
        if (lane == 0) out[b * NCLS + c] = p + b_cls[c];
    }
}

// =====================================================================
static const int SMEM_BYTES =
    (GSZ * WPITCH + 16 * WPITCH) * 4 +      // Wst + Ast
    2 * 8 * RPITCH * 2 * 4 +                 // double-buffered ring
    GSZ * 4 +                                // bias_s
    (HSZ + GSZ) * 8;                         // h_s + gate_s

extern "C" void kernel_launch(void* const* d_in, const int* in_sizes, int n_in,
                              void* d_out, int out_size) {
    const float* x     = (const float*)d_in[0];
    const float* W_ih  = (const float*)d_in[1];
    const float* W_hh  = (const float*)d_in[2];
    const float* b_ih  = (const float*)d_in[3];
    const float* b_hh  = (const float*)d_in[4];
    const float* W_cls = (const float*)d_in[5];
    const float* b_cls = (const float*)d_in[6];
    float* out = (float*)d_out;

    cudaFuncSetAttribute(lstm_fused_kernel,
                         cudaFuncAttributeMaxDynamicSharedMemorySize, SMEM_BYTES);
    lstm_fused_kernel<<<NBP, NTHR, SMEM_BYTES>>>(x, W_ih, W_hh, b_ih, b_hh);
    cls_kernel<<<BATCH, 32>>>(W_cls, b_cls, out);
}